// round 1
// baseline (speedup 1.0000x reference)
#include <cuda_runtime.h>
#include <math.h>
#include <stdint.h>

#define BB 64
#define EE 1024
#define HH 1024
#define LL 512
#define VV 50257

// ---------------- scratch (device globals, no allocation) ----------------
__device__ float g_emb[BB * EE];
__device__ float g_attnw[BB * LL];
__device__ float g_attnapp[BB * HH];
__device__ float g_x[BB * EE];
__device__ float g_partA[4 * BB * 3 * HH];   // 786432 floats (covers attn 8*64*512, comb 8*64*1024, gi 4*64*3072)
__device__ float g_partB[4 * BB * 3 * HH];   // gh partials

// ---------------- embedding gather ----------------
__global__ void k_gather(const int* __restrict__ ids, const float* __restrict__ embW,
                         float* __restrict__ out) {
    int b = blockIdx.x;
    const float* src = embW + (size_t)ids[b] * EE;
    for (int i = threadIdx.x; i < EE; i += blockDim.x) out[b * EE + i] = src[i];
}

// ---------------- generic f32x2 GEMM: C[64,N] = A[64,K] @ W[N,K]^T ----------------
// A is virtual concat of A1[64,K1] and A2[64,K-K1].
// direct=1: C = dot + bias (single k-split). direct=0: write partial [split][64][N].
// blockIdx.z==1 selects the alternate (A1b, Wb, Cb) problem (used for GRU gh).
__launch_bounds__(128)
__global__ void gemm_f32x2(const float* __restrict__ A1, const float* __restrict__ A2,
                           int K1, int K,
                           const float* __restrict__ W, const float* __restrict__ bias,
                           float* __restrict__ C, int N, int kChunk, int direct,
                           const float* A1b, const float* Wb, float* Cb) {
    if (blockIdx.z == 1) { A1 = A1b; W = Wb; C = Cb; }

    __shared__ float As[32 * 66];    // [k][m], padded row 66
    __shared__ float Ws[32 * 128];   // [k][n]

    const int tid = threadIdx.x;
    const int tn = tid & 15;
    const int tm = tid >> 4;
    const int m0 = tm * 8;
    const int n0loc = tn * 8;
    const int nBase = blockIdx.x * 128;
    const int kBase = blockIdx.y * kChunk;

    unsigned long long acc[4][8];
#pragma unroll
    for (int i = 0; i < 4; i++)
#pragma unroll
        for (int j = 0; j < 8; j++) acc[i][j] = 0ULL;

    for (int kt = 0; kt < kChunk; kt += 32) {
        const int k0 = kBase + kt;
        __syncthreads();
        // stage A tile (64 x 32) -> As[k][m]
#pragma unroll
        for (int i = 0; i < 16; i++) {
            int f = tid + 128 * i;           // f = m*32 + k
            int m = f >> 5;
            int k = f & 31;
            int kk = k0 + k;
            float v = (kk < K1) ? A1[m * K1 + kk] : A2[m * (K - K1) + (kk - K1)];
            As[k * 66 + m] = v;
        }
        // stage W tile (128 rows x 32 cols) -> Ws[k][n]
        {
            int n = nBase + tid;
            bool ok = (n < N);
            const float* wr = W + (size_t)n * K + k0;
#pragma unroll
            for (int i = 0; i < 8; i++) {
                float4 v;
                if (ok) v = *reinterpret_cast<const float4*>(wr + i * 4);
                else    v = make_float4(0.f, 0.f, 0.f, 0.f);
                Ws[(i * 4 + 0) * 128 + tid] = v.x;
                Ws[(i * 4 + 1) * 128 + tid] = v.y;
                Ws[(i * 4 + 2) * 128 + tid] = v.z;
                Ws[(i * 4 + 3) * 128 + tid] = v.w;
            }
        }
        __syncthreads();
#pragma unroll 4
        for (int kk = 0; kk < 32; kk++) {
            unsigned long long a2[4];
            const float* ar = As + kk * 66 + m0;
#pragma unroll
            for (int i = 0; i < 4; i++)
                a2[i] = *reinterpret_cast<const unsigned long long*>(ar + 2 * i);
            const float* br = Ws + kk * 128 + n0loc;
            float4 b0 = *reinterpret_cast<const float4*>(br);
            float4 b1 = *reinterpret_cast<const float4*>(br + 4);
            float bv[8] = {b0.x, b0.y, b0.z, b0.w, b1.x, b1.y, b1.z, b1.w};
#pragma unroll
            for (int j = 0; j < 8; j++) {
                unsigned long long b2;
                asm("mov.b64 %0, {%1, %1};" : "=l"(b2) : "f"(bv[j]));
#pragma unroll
                for (int i = 0; i < 4; i++)
                    asm("fma.rn.f32x2 %0, %1, %2, %0;"
                        : "+l"(acc[i][j]) : "l"(a2[i]), "l"(b2));
            }
        }
    }

    // epilogue
    float* Cout = direct ? C : (C + (size_t)blockIdx.y * 64 * N);
#pragma unroll
    for (int j = 0; j < 8; j++) {
        int n = nBase + n0loc + j;
        if (n >= N) continue;
        float bb = direct ? bias[n] : 0.f;
#pragma unroll
        for (int i = 0; i < 4; i++) {
            unsigned long long u = acc[i][j];
            float lo = __uint_as_float((unsigned)u);
            float hi = __uint_as_float((unsigned)(u >> 32));
            int m = m0 + 2 * i;
            Cout[(size_t)m * N + n]       = lo + bb;
            Cout[(size_t)(m + 1) * N + n] = hi + bb;
        }
    }
}

// ---------------- attn logits reduce + softmax over L=512 ----------------
__global__ void k_attn_softmax(const float* __restrict__ part, const float* __restrict__ bias,
                               float* __restrict__ wout) {
    int b = blockIdx.x;
    int l = threadIdx.x;   // 512 threads
    float v = bias[l];
#pragma unroll
    for (int s = 0; s < 8; s++) v += part[((size_t)s * BB + b) * LL + l];

    __shared__ float red[32];
    float m = v;
#pragma unroll
    for (int o = 16; o > 0; o >>= 1) m = fmaxf(m, __shfl_xor_sync(~0u, m, o));
    if ((threadIdx.x & 31) == 0) red[threadIdx.x >> 5] = m;
    __syncthreads();
    if (threadIdx.x < 32) {
        float t = (threadIdx.x < 16) ? red[threadIdx.x] : -1e30f;
#pragma unroll
        for (int o = 8; o > 0; o >>= 1) t = fmaxf(t, __shfl_xor_sync(~0u, t, o));
        if (threadIdx.x == 0) red[0] = t;
    }
    __syncthreads();
    float rowmax = red[0];
    __syncthreads();
    float e = expf(v - rowmax);
    float ssum = e;
#pragma unroll
    for (int o = 16; o > 0; o >>= 1) ssum += __shfl_xor_sync(~0u, ssum, o);
    if ((threadIdx.x & 31) == 0) red[threadIdx.x >> 5] = ssum;
    __syncthreads();
    if (threadIdx.x < 32) {
        float t = (threadIdx.x < 16) ? red[threadIdx.x] : 0.f;
#pragma unroll
        for (int o = 8; o > 0; o >>= 1) t += __shfl_xor_sync(~0u, t, o);
        if (threadIdx.x == 0) red[0] = t;
    }
    __syncthreads();
    wout[b * LL + l] = e / red[0];
}

// ---------------- attn_applied[b,d] = sum_l w[b,l] * enc[b,l,d] ----------------
__global__ void k_attnapp(const float* __restrict__ w, const float* __restrict__ enc,
                          float* __restrict__ out) {
    int b = blockIdx.y;
    int d = blockIdx.x * 256 + threadIdx.x;
    __shared__ float ws[LL];
    for (int i = threadIdx.x; i < LL; i += 256) ws[i] = w[b * LL + i];
    __syncthreads();
    const float* ep = enc + (size_t)b * LL * HH + d;
    float acc = 0.f;
#pragma unroll 4
    for (int l = 0; l < LL; l++) acc += ws[l] * ep[(size_t)l * HH];
    out[b * HH + d] = acc;
}

// ---------------- combine reduce + bias + relu ----------------
__global__ void k_combrelu(const float* __restrict__ part, const float* __restrict__ bias,
                           float* __restrict__ out) {
    int idx = blockIdx.x * 256 + threadIdx.x;   // 64*1024
    int e = idx & (EE - 1);
    float v = bias[e];
#pragma unroll
    for (int s = 0; s < 8; s++) v += part[(size_t)s * BB * EE + idx];
    out[idx] = fmaxf(v, 0.f);
}

// ---------------- GRU gates: reduce partials + gate math ----------------
__global__ void k_gru(const float* __restrict__ pgi, const float* __restrict__ pgh,
                      const float* __restrict__ bih, const float* __restrict__ bhh,
                      const float* __restrict__ hidden, float* __restrict__ newh) {
    int idx = blockIdx.x * 256 + threadIdx.x;   // 64*1024
    int b = idx >> 10;
    int h = idx & 1023;
    const int N3 = 3 * HH;
    float ir = bih[h], iz = bih[HH + h], in_ = bih[2 * HH + h];
    float hr = bhh[h], hz = bhh[HH + h], hn = bhh[2 * HH + h];
#pragma unroll
    for (int s = 0; s < 4; s++) {
        size_t base = ((size_t)s * BB + b) * N3;
        ir  += pgi[base + h];
        iz  += pgi[base + HH + h];
        in_ += pgi[base + 2 * HH + h];
        hr  += pgh[base + h];
        hz  += pgh[base + HH + h];
        hn  += pgh[base + 2 * HH + h];
    }
    float r = 1.f / (1.f + expf(-(ir + hr)));
    float z = 1.f / (1.f + expf(-(iz + hz)));
    float n = tanhf(in_ + r * hn);
    newh[idx] = (1.f - z) * n + z * hidden[idx];
}

// ---------------- in-place log_softmax over V per row ----------------
__global__ void k_logsoftmax(float* __restrict__ out) {
    int b = blockIdx.x;
    float* row = out + (size_t)b * VV;
    __shared__ float red[32];
    float m = -1e30f;
    for (int i = threadIdx.x; i < VV; i += 1024) m = fmaxf(m, row[i]);
#pragma unroll
    for (int o = 16; o > 0; o >>= 1) m = fmaxf(m, __shfl_xor_sync(~0u, m, o));
    if ((threadIdx.x & 31) == 0) red[threadIdx.x >> 5] = m;
    __syncthreads();
    if (threadIdx.x < 32) {
        float t = red[threadIdx.x];
#pragma unroll
        for (int o = 16; o > 0; o >>= 1) t = fmaxf(t, __shfl_xor_sync(~0u, t, o));
        if (threadIdx.x == 0) red[0] = t;
    }
    __syncthreads();
    float rowmax = red[0];
    __syncthreads();
    float s = 0.f;
    for (int i = threadIdx.x; i < VV; i += 1024) s += expf(row[i] - rowmax);
#pragma unroll
    for (int o = 16; o > 0; o >>= 1) s += __shfl_xor_sync(~0u, s, o);
    if ((threadIdx.x & 31) == 0) red[threadIdx.x >> 5] = s;
    __syncthreads();
    if (threadIdx.x < 32) {
        float t = red[threadIdx.x];
#pragma unroll
        for (int o = 16; o > 0; o >>= 1) t += __shfl_xor_sync(~0u, t, o);
        if (threadIdx.x == 0) red[0] = t;
    }
    __syncthreads();
    float lse = rowmax + logf(red[0]);
    for (int i = threadIdx.x; i < VV; i += 1024) row[i] -= lse;
}

// ---------------- launch ----------------
extern "C" void kernel_launch(void* const* d_in, const int* in_sizes, int n_in,
                              void* d_out, int out_size) {
    const int*   ids    = (const int*)  d_in[0];
    const float* hidden = (const float*)d_in[1];
    const float* enc    = (const float*)d_in[2];
    const float* embW   = (const float*)d_in[3];
    const float* attnW  = (const float*)d_in[4];
    const float* attnb  = (const float*)d_in[5];
    const float* combW  = (const float*)d_in[6];
    const float* combb  = (const float*)d_in[7];
    const float* Wih    = (const float*)d_in[8];
    const float* Whh    = (const float*)d_in[9];
    const float* bih    = (const float*)d_in[10];
    const float* bhh    = (const float*)d_in[11];
    const float* outW   = (const float*)d_in[12];
    const float* outb   = (const float*)d_in[13];

    float* out  = (float*)d_out;              // [64, 50257] log-probs
    float* newh = out + (size_t)BB * VV;      // [64, 1024] new hidden (2nd output)

    float *p_emb, *p_attnw, *p_attnapp, *p_x, *p_pa, *p_pb;
    cudaGetSymbolAddress((void**)&p_emb, g_emb);
    cudaGetSymbolAddress((void**)&p_attnw, g_attnw);
    cudaGetSymbolAddress((void**)&p_attnapp, g_attnapp);
    cudaGetSymbolAddress((void**)&p_x, g_x);
    cudaGetSymbolAddress((void**)&p_pa, g_partA);
    cudaGetSymbolAddress((void**)&p_pb, g_partB);

    // 1. embedding gather
    k_gather<<<BB, 256>>>(ids, embW, p_emb);

    // 2. attn logits: [64,512] = cat(emb,hidden) @ attn_W^T  (split-K 8)
    gemm_f32x2<<<dim3(4, 8, 1), 128>>>(p_emb, hidden, EE, EE + HH, attnW, nullptr,
                                       p_pa, LL, 256, 0, nullptr, nullptr, nullptr);

    // 3. reduce + bias + softmax over L
    k_attn_softmax<<<BB, 512>>>(p_pa, attnb, p_attnw);

    // 4. attention context over encoder outputs
    k_attnapp<<<dim3(HH / 256, BB), 256>>>(p_attnw, enc, p_attnapp);

    // 5. combine: [64,1024] = cat(emb, attn_applied) @ comb_W^T (split-K 8)
    gemm_f32x2<<<dim3(8, 8, 1), 128>>>(p_emb, p_attnapp, EE, EE + HH, combW, nullptr,
                                       p_pa, EE, 256, 0, nullptr, nullptr, nullptr);

    // 6. reduce + bias + relu
    k_combrelu<<<(BB * EE) / 256, 256>>>(p_pa, combb, p_x);

    // 7. GRU gi (z=0: x@Wih^T) and gh (z=1: hidden@Whh^T), split-K 4 each
    gemm_f32x2<<<dim3(24, 4, 2), 128>>>(p_x, nullptr, HH, HH, Wih, nullptr,
                                        p_pa, 3 * HH, 256, 0,
                                        hidden, Whh, p_pb);

    // 8. GRU gate fusion -> new hidden (2nd output)
    k_gru<<<(BB * HH) / 256, 256>>>(p_pa, p_pb, bih, bhh, hidden, newh);

    // 9. output projection: [64,50257] = newh @ out_W^T + out_b (direct, single split)
    gemm_f32x2<<<dim3((VV + 127) / 128, 1, 1), 128>>>(newh, nullptr, HH, HH, outW, outb,
                                                      out, VV, HH, 1,
                                                      nullptr, nullptr, nullptr);

    // 10. in-place log_softmax over vocab
    k_logsoftmax<<<BB, 1024>>>(out);
}

// round 2
// speedup vs baseline: 2.0809x; 2.0809x over previous
#include <cuda_runtime.h>
#include <math.h>
#include <stdint.h>

#define BB 64
#define EE 1024
#define HH 1024
#define LL 512
#define VV 50257

// ---------------- scratch (device globals, no allocation) ----------------
__device__ float g_emb[BB * EE];
__device__ float g_attnw[BB * LL];
__device__ float g_attnapp[BB * HH];
__device__ float g_x[BB * EE];
__device__ float g_partA[8 * BB * 3 * HH];   // 1.57M floats: covers comb 16*64*1024, gru 8*64*3072, attn 16*64*512
__device__ float g_partB[8 * BB * 3 * HH];   // gh partials + attnapp partials (8*64*1024)
__device__ float g_lsm[64 * 8 * 2 + 64];     // [0,512) m, [512,1024) s, [1024,1088) lse

// ---------------- embedding gather ----------------
__global__ void k_gather(const int* __restrict__ ids, const float* __restrict__ embW,
                         float* __restrict__ out) {
    int b = blockIdx.x;
    const float* src = embW + (size_t)ids[b] * EE;
    for (int i = threadIdx.x; i < EE; i += blockDim.x) out[b * EE + i] = src[i];
}

// ---------------- generic f32x2 GEMM: partials C[s][64][N] = A[64,Kchunk] @ W^T ----------------
__launch_bounds__(128)
__global__ void gemm_f32x2(const float* __restrict__ A1, const float* __restrict__ A2,
                           int K1, int K,
                           const float* __restrict__ W,
                           float* __restrict__ C, int N, int kChunk,
                           const float* A1b, const float* Wb, float* Cb) {
    if (blockIdx.z == 1) { A1 = A1b; W = Wb; C = Cb; }

    __shared__ float As[32 * 66];    // [k][m], padded row 66
    __shared__ float Ws[32 * 128];   // [k][n]

    const int tid = threadIdx.x;
    const int tn = tid & 15;
    const int tm = tid >> 4;
    const int m0 = tm * 8;
    const int n0loc = tn * 8;
    const int nBase = blockIdx.x * 128;
    const int kBase = blockIdx.y * kChunk;

    unsigned long long acc[4][8];
#pragma unroll
    for (int i = 0; i < 4; i++)
#pragma unroll
        for (int j = 0; j < 8; j++) acc[i][j] = 0ULL;

    for (int kt = 0; kt < kChunk; kt += 32) {
        const int k0 = kBase + kt;
        __syncthreads();
#pragma unroll
        for (int i = 0; i < 16; i++) {
            int f = tid + 128 * i;           // f = m*32 + k
            int m = f >> 5;
            int k = f & 31;
            int kk = k0 + k;
            float v = (kk < K1) ? A1[m * K1 + kk] : A2[m * (K - K1) + (kk - K1)];
            As[k * 66 + m] = v;
        }
        {
            int n = nBase + tid;
            bool ok = (n < N);
            const float* wr = W + (size_t)n * K + k0;
#pragma unroll
            for (int i = 0; i < 8; i++) {
                float4 v;
                if (ok) v = *reinterpret_cast<const float4*>(wr + i * 4);
                else    v = make_float4(0.f, 0.f, 0.f, 0.f);
                Ws[(i * 4 + 0) * 128 + tid] = v.x;
                Ws[(i * 4 + 1) * 128 + tid] = v.y;
                Ws[(i * 4 + 2) * 128 + tid] = v.z;
                Ws[(i * 4 + 3) * 128 + tid] = v.w;
            }
        }
        __syncthreads();
#pragma unroll 4
        for (int kk = 0; kk < 32; kk++) {
            unsigned long long a2[4];
            const float* ar = As + kk * 66 + m0;
#pragma unroll
            for (int i = 0; i < 4; i++)
                a2[i] = *reinterpret_cast<const unsigned long long*>(ar + 2 * i);
            const float* br = Ws + kk * 128 + n0loc;
            float4 b0 = *reinterpret_cast<const float4*>(br);
            float4 b1 = *reinterpret_cast<const float4*>(br + 4);
            float bv[8] = {b0.x, b0.y, b0.z, b0.w, b1.x, b1.y, b1.z, b1.w};
#pragma unroll
            for (int j = 0; j < 8; j++) {
                unsigned long long b2;
                asm("mov.b64 %0, {%1, %1};" : "=l"(b2) : "f"(bv[j]));
#pragma unroll
                for (int i = 0; i < 4; i++)
                    asm("fma.rn.f32x2 %0, %1, %2, %0;"
                        : "+l"(acc[i][j]) : "l"(a2[i]), "l"(b2));
            }
        }
    }

    float* Cout = C + (size_t)blockIdx.y * 64 * N;
#pragma unroll
    for (int j = 0; j < 8; j++) {
        int n = nBase + n0loc + j;
        if (n >= N) continue;
#pragma unroll
        for (int i = 0; i < 4; i++) {
            unsigned long long u = acc[i][j];
            float lo = __uint_as_float((unsigned)u);
            float hi = __uint_as_float((unsigned)(u >> 32));
            int m = m0 + 2 * i;
            Cout[(size_t)m * N + n]       = lo;
            Cout[(size_t)(m + 1) * N + n] = hi;
        }
    }
}

// ---------------- attn logits reduce + softmax over L=512 ----------------
__global__ void k_attn_softmax(const float* __restrict__ part, const float* __restrict__ bias,
                               float* __restrict__ wout, int S) {
    int b = blockIdx.x;
    int l = threadIdx.x;   // 512 threads
    float v = bias[l];
    for (int s = 0; s < S; s++) v += part[((size_t)s * BB + b) * LL + l];

    __shared__ float red[32];
    float m = v;
#pragma unroll
    for (int o = 16; o > 0; o >>= 1) m = fmaxf(m, __shfl_xor_sync(~0u, m, o));
    if ((threadIdx.x & 31) == 0) red[threadIdx.x >> 5] = m;
    __syncthreads();
    if (threadIdx.x < 32) {
        float t = (threadIdx.x < 16) ? red[threadIdx.x] : -1e30f;
#pragma unroll
        for (int o = 8; o > 0; o >>= 1) t = fmaxf(t, __shfl_xor_sync(~0u, t, o));
        if (threadIdx.x == 0) red[0] = t;
    }
    __syncthreads();
    float rowmax = red[0];
    __syncthreads();
    float e = expf(v - rowmax);
    float ssum = e;
#pragma unroll
    for (int o = 16; o > 0; o >>= 1) ssum += __shfl_xor_sync(~0u, ssum, o);
    if ((threadIdx.x & 31) == 0) red[threadIdx.x >> 5] = ssum;
    __syncthreads();
    if (threadIdx.x < 32) {
        float t = (threadIdx.x < 16) ? red[threadIdx.x] : 0.f;
#pragma unroll
        for (int o = 8; o > 0; o >>= 1) t += __shfl_xor_sync(~0u, t, o);
        if (threadIdx.x == 0) red[0] = t;
    }
    __syncthreads();
    wout[b * LL + l] = e / red[0];
}

// ---------------- attn context partials: part[s][b][d] over L-slice ----------------
__global__ void k_attnapp_part(const float* __restrict__ w, const float* __restrict__ enc,
                               float* __restrict__ part) {
    int s = blockIdx.x;      // 8 slices of 64 L-rows
    int b = blockIdx.y;
    int d4 = threadIdx.x;    // 256 vec4 columns
    __shared__ float ws[64];
    if (threadIdx.x < 64) ws[threadIdx.x] = w[b * LL + s * 64 + threadIdx.x];
    __syncthreads();
    const float4* ep = reinterpret_cast<const float4*>(enc + (size_t)b * LL * HH + (size_t)s * 64 * HH) + d4;
    float4 acc = make_float4(0.f, 0.f, 0.f, 0.f);
#pragma unroll 8
    for (int l = 0; l < 64; l++) {
        float4 v = ep[l * (HH / 4)];
        float c = ws[l];
        acc.x += c * v.x; acc.y += c * v.y; acc.z += c * v.z; acc.w += c * v.w;
    }
    reinterpret_cast<float4*>(part + ((size_t)s * BB + b) * HH)[d4] = acc;
}

__global__ void k_attnred(const float* __restrict__ part, float* __restrict__ out) {
    int i = blockIdx.x * 256 + threadIdx.x;   // 64*1024
    float v = 0.f;
#pragma unroll
    for (int s = 0; s < 8; s++) v += part[(size_t)s * BB * HH + i];
    out[i] = v;
}

// ---------------- combine reduce + bias + relu ----------------
__global__ void k_combrelu(const float* __restrict__ part, const float* __restrict__ bias,
                           float* __restrict__ out, int S) {
    int idx = blockIdx.x * 256 + threadIdx.x;   // 64*1024
    int e = idx & (EE - 1);
    float v = bias[e];
    for (int s = 0; s < S; s++) v += part[(size_t)s * BB * EE + idx];
    out[idx] = fmaxf(v, 0.f);
}

// ---------------- GRU gates: reduce partials + gate math ----------------
__global__ void k_gru(const float* __restrict__ pgi, const float* __restrict__ pgh,
                      const float* __restrict__ bih, const float* __restrict__ bhh,
                      const float* __restrict__ hidden, float* __restrict__ newh, int S) {
    int idx = blockIdx.x * 256 + threadIdx.x;   // 64*1024
    int b = idx >> 10;
    int h = idx & 1023;
    const int N3 = 3 * HH;
    float ir = bih[h], iz = bih[HH + h], in_ = bih[2 * HH + h];
    float hr = bhh[h], hz = bhh[HH + h], hn = bhh[2 * HH + h];
    for (int s = 0; s < S; s++) {
        size_t base = ((size_t)s * BB + b) * N3;
        ir  += pgi[base + h];
        iz  += pgi[base + HH + h];
        in_ += pgi[base + 2 * HH + h];
        hr  += pgh[base + h];
        hz  += pgh[base + HH + h];
        hn  += pgh[base + 2 * HH + h];
    }
    float r = 1.f / (1.f + expf(-(ir + hr)));
    float z = 1.f / (1.f + expf(-(iz + hz)));
    float n = tanhf(in_ + r * hn);
    newh[idx] = (1.f - z) * n + z * hidden[idx];
}

// ================= fat output GEMM: bf16 mma.sync tensor cores =================
// C[64, VV] = A[64,1024] @ W[VV,1024]^T + bias.  fp32 inputs converted to bf16
// in smem; fp32 accumulate. BM=64 BN=128 BK=32, 256 threads (8 warps 2m x 4n).
__device__ __forceinline__ uint32_t pack_bf16(float lo, float hi) {
    uint32_t r;
    asm("cvt.rn.bf16x2.f32 %0, %1, %2;" : "=r"(r) : "f"(hi), "f"(lo));
    return r;
}

// byte offset in block-contiguous layout: 128B atom blocks, XOR row-slotting
__device__ __forceinline__ int tile_off(int row, int k) {
    int c = k >> 3;                      // k-chunk 0..3
    int blk = ((row >> 3) << 2) + c;
    int slot = ((row & 7) ^ (c << 1)) & 7;
    return blk * 128 + slot * 16 + (k & 7) * 2;
}

__global__ __launch_bounds__(256) void k_outproj(const float* __restrict__ A,
                                                 const float* __restrict__ W,
                                                 const float* __restrict__ bias,
                                                 float* __restrict__ C) {
    __shared__ __align__(16) uint32_t smA[1024];  // 64x32 bf16 = 4KB
    __shared__ __align__(16) uint32_t smB[2048];  // 128x32 bf16 = 8KB

    const int tid = threadIdx.x;
    const int lane = tid & 31, wid = tid >> 5;
    const int wm = wid & 1, wn = wid >> 1;      // warp grid 2(m) x 4(n)
    const int nBase = blockIdx.x * 128;

    uint32_t aBase = (uint32_t)__cvta_generic_to_shared(smA);
    uint32_t bBase = (uint32_t)__cvta_generic_to_shared(smB);

    // precompute ldmatrix addresses (smem layout constant across k-tiles)
    uint32_t aAddr[2][2], bAddr[4][2];
#pragma unroll
    for (int ma = 0; ma < 2; ma++)
#pragma unroll
        for (int ka = 0; ka < 2; ka++) {
            int row = wm * 32 + ma * 16 + ((lane >> 3) & 1) * 8 + (lane & 7);
            int c = ka * 2 + (lane >> 4);
            aAddr[ma][ka] = aBase + (((row >> 3) << 2) + c) * 128 + (((row & 7) ^ (c << 1)) & 7) * 16;
        }
#pragma unroll
    for (int na = 0; na < 4; na++)
#pragma unroll
        for (int ka = 0; ka < 2; ka++) {
            int l = lane & 15;
            int n = wn * 32 + na * 8 + (l & 7);
            int c = ka * 2 + (l >> 3);
            bAddr[na][ka] = bBase + (((n >> 3) << 2) + c) * 128 + (((n & 7) ^ (c << 1)) & 7) * 16;
        }

    float acc[2][4][4];
#pragma unroll
    for (int i = 0; i < 2; i++)
#pragma unroll
        for (int j = 0; j < 4; j++)
#pragma unroll
            for (int q = 0; q < 4; q++) acc[i][j][q] = 0.f;

    float4 ra[2], rb[4];
    // preload tile 0
#pragma unroll
    for (int s = 0; s < 2; s++) {
        int idx = tid + 256 * s;
        ra[s] = *reinterpret_cast<const float4*>(A + (idx >> 3) * 1024 + (idx & 7) * 4);
    }
#pragma unroll
    for (int s = 0; s < 4; s++) {
        int idx = tid + 256 * s;
        int ng = nBase + (idx >> 3);
        if (ng < VV)
            rb[s] = *reinterpret_cast<const float4*>(W + (size_t)ng * 1024 + (idx & 7) * 4);
        else
            rb[s] = make_float4(0.f, 0.f, 0.f, 0.f);
    }

    for (int kt = 0; kt < 32; kt++) {
        __syncthreads();
        // store staged tile (convert fp32 -> bf16, 2-way-min bank pattern)
#pragma unroll
        for (int s = 0; s < 2; s++) {
            int idx = tid + 256 * s;
            int m = idx >> 3, kq = idx & 7;
            uint2 v = make_uint2(pack_bf16(ra[s].x, ra[s].y), pack_bf16(ra[s].z, ra[s].w));
            *reinterpret_cast<uint2*>(reinterpret_cast<char*>(smA) + tile_off(m, kq * 4)) = v;
        }
#pragma unroll
        for (int s = 0; s < 4; s++) {
            int idx = tid + 256 * s;
            int n = idx >> 3, kq = idx & 7;
            uint2 v = make_uint2(pack_bf16(rb[s].x, rb[s].y), pack_bf16(rb[s].z, rb[s].w));
            *reinterpret_cast<uint2*>(reinterpret_cast<char*>(smB) + tile_off(n, kq * 4)) = v;
        }
        __syncthreads();

        // prefetch next tile while computing this one
        if (kt + 1 < 32) {
            int k0 = (kt + 1) * 32;
#pragma unroll
            for (int s = 0; s < 2; s++) {
                int idx = tid + 256 * s;
                ra[s] = *reinterpret_cast<const float4*>(A + (idx >> 3) * 1024 + k0 + (idx & 7) * 4);
            }
#pragma unroll
            for (int s = 0; s < 4; s++) {
                int idx = tid + 256 * s;
                int ng = nBase + (idx >> 3);
                if (ng < VV)
                    rb[s] = *reinterpret_cast<const float4*>(W + (size_t)ng * 1024 + k0 + (idx & 7) * 4);
                else
                    rb[s] = make_float4(0.f, 0.f, 0.f, 0.f);
            }
        }

        // compute
#pragma unroll
        for (int ka = 0; ka < 2; ka++) {
            uint32_t af[2][4];
#pragma unroll
            for (int ma = 0; ma < 2; ma++)
                asm volatile("ldmatrix.sync.aligned.m8n8.x4.shared.b16 {%0,%1,%2,%3}, [%4];"
                             : "=r"(af[ma][0]), "=r"(af[ma][1]), "=r"(af[ma][2]), "=r"(af[ma][3])
                             : "r"(aAddr[ma][ka]));
            uint32_t bf[4][2];
#pragma unroll
            for (int na = 0; na < 4; na++)
                asm volatile("ldmatrix.sync.aligned.m8n8.x2.shared.b16 {%0,%1}, [%2];"
                             : "=r"(bf[na][0]), "=r"(bf[na][1])
                             : "r"(bAddr[na][ka]));
#pragma unroll
            for (int ma = 0; ma < 2; ma++)
#pragma unroll
                for (int na = 0; na < 4; na++)
                    asm volatile(
                        "mma.sync.aligned.m16n8k16.row.col.f32.bf16.bf16.f32 "
                        "{%0,%1,%2,%3}, {%4,%5,%6,%7}, {%8,%9}, {%0,%1,%2,%3};"
                        : "+f"(acc[ma][na][0]), "+f"(acc[ma][na][1]),
                          "+f"(acc[ma][na][2]), "+f"(acc[ma][na][3])
                        : "r"(af[ma][0]), "r"(af[ma][1]), "r"(af[ma][2]), "r"(af[ma][3]),
                          "r"(bf[na][0]), "r"(bf[na][1]));
        }
    }

    // epilogue
    int g = lane >> 2, tig = lane & 3;
#pragma unroll
    for (int ma = 0; ma < 2; ma++)
#pragma unroll
        for (int na = 0; na < 4; na++) {
            int col = nBase + wn * 32 + na * 8 + tig * 2;
            int r0 = wm * 32 + ma * 16 + g;
            if (col < VV) {
                float b0 = bias[col];
                C[(size_t)r0 * VV + col]       = acc[ma][na][0] + b0;
                C[(size_t)(r0 + 8) * VV + col] = acc[ma][na][2] + b0;
                if (col + 1 < VV) {
                    float b1 = bias[col + 1];
                    C[(size_t)r0 * VV + col + 1]       = acc[ma][na][1] + b1;
                    C[(size_t)(r0 + 8) * VV + col + 1] = acc[ma][na][3] + b1;
                }
            }
        }
}

// ---------------- split log_softmax ----------------
__global__ void k_lsm_part(const float* __restrict__ out, float* __restrict__ lsm) {
    int c = blockIdx.x;          // 8 chunks
    int b = blockIdx.y;
    const int CH = (VV + 7) / 8; // 6283
    int start = c * CH;
    int end = min(start + CH, VV);
    const float* row = out + (size_t)b * VV;

    __shared__ float red[32];
    float m = -1e30f;
    for (int i = start + threadIdx.x; i < end; i += 256) m = fmaxf(m, row[i]);
#pragma unroll
    for (int o = 16; o > 0; o >>= 1) m = fmaxf(m, __shfl_xor_sync(~0u, m, o));
    if ((threadIdx.x & 31) == 0) red[threadIdx.x >> 5] = m;
    __syncthreads();
    if (threadIdx.x < 32) {
        float t = (threadIdx.x < 8) ? red[threadIdx.x] : -1e30f;
#pragma unroll
        for (int o = 4; o > 0; o >>= 1) t = fmaxf(t, __shfl_xor_sync(~0u, t, o));
        if (threadIdx.x == 0) red[0] = t;
    }
    __syncthreads();
    float bm = red[0];
    __syncthreads();

    float s = 0.f;
    for (int i = start + threadIdx.x; i < end; i += 256) s += __expf(row[i] - bm);
#pragma unroll
    for (int o = 16; o > 0; o >>= 1) s += __shfl_xor_sync(~0u, s, o);
    if ((threadIdx.x & 31) == 0) red[threadIdx.x >> 5] = s;
    __syncthreads();
    if (threadIdx.x < 32) {
        float t = (threadIdx.x < 8) ? red[threadIdx.x] : 0.f;
#pragma unroll
        for (int o = 4; o > 0; o >>= 1) t += __shfl_xor_sync(~0u, t, o);
        if (threadIdx.x == 0) {
            lsm[b * 8 + c] = bm;            // max
            lsm[512 + b * 8 + c] = t;       // sum
        }
    }
}

__global__ void k_lsm_comb(float* __restrict__ lsm) {
    int b = blockIdx.x;
    if (threadIdx.x == 0) {
        float m = -1e30f;
        for (int c = 0; c < 8; c++) m = fmaxf(m, lsm[b * 8 + c]);
        float s = 0.f;
        for (int c = 0; c < 8; c++) s += lsm[512 + b * 8 + c] * __expf(lsm[b * 8 + c] - m);
        lsm[1024 + b] = m + logf(s);
    }
}

__global__ void k_lsm_write(float* __restrict__ out, const float* __restrict__ lsm) {
    int c = blockIdx.x;
    int b = blockIdx.y;
    const int CH = (VV + 7) / 8;
    int start = c * CH;
    int end = min(start + CH, VV);
    float lse = lsm[1024 + b];
    float* row = out + (size_t)b * VV;
    for (int i = start + threadIdx.x; i < end; i += 256) row[i] -= lse;
}

// ---------------- launch ----------------
extern "C" void kernel_launch(void* const* d_in, const int* in_sizes, int n_in,
                              void* d_out, int out_size) {
    const int*   ids    = (const int*)  d_in[0];
    const float* hidden = (const float*)d_in[1];
    const float* enc    = (const float*)d_in[2];
    const float* embW   = (const float*)d_in[3];
    const float* attnW  = (const float*)d_in[4];
    const float* attnb  = (const float*)d_in[5];
    const float* combW  = (const float*)d_in[6];
    const float* combb  = (const float*)d_in[7];
    const float* Wih    = (const float*)d_in[8];
    const float* Whh    = (const float*)d_in[9];
    const float* bih    = (const float*)d_in[10];
    const float* bhh    = (const float*)d_in[11];
    const float* outW   = (const float*)d_in[12];
    const float* outb   = (const float*)d_in[13];

    float* out  = (float*)d_out;              // [64, 50257] log-probs
    float* newh = out + (size_t)BB * VV;      // [64, 1024] new hidden

    float *p_emb, *p_attnw, *p_attnapp, *p_x, *p_pa, *p_pb, *p_lsm;
    cudaGetSymbolAddress((void**)&p_emb, g_emb);
    cudaGetSymbolAddress((void**)&p_attnw, g_attnw);
    cudaGetSymbolAddress((void**)&p_attnapp, g_attnapp);
    cudaGetSymbolAddress((void**)&p_x, g_x);
    cudaGetSymbolAddress((void**)&p_pa, g_partA);
    cudaGetSymbolAddress((void**)&p_pb, g_partB);
    cudaGetSymbolAddress((void**)&p_lsm, g_lsm);

    // 1. embedding gather
    k_gather<<<BB, 256>>>(ids, embW, p_emb);

    // 2. attn logits: cat(emb,hidden) @ attn_W^T, split-K 16
    gemm_f32x2<<<dim3(4, 16, 1), 128>>>(p_emb, hidden, EE, EE + HH, attnW,
                                        p_pa, LL, 128, nullptr, nullptr, nullptr);

    // 3. reduce + bias + softmax over L
    k_attn_softmax<<<BB, 512>>>(p_pa, attnb, p_attnw, 16);

    // 4. attention context (split-L 8 partials + reduce)
    k_attnapp_part<<<dim3(8, BB), 256>>>(p_attnw, enc, p_pb);
    k_attnred<<<(BB * HH) / 256, 256>>>(p_pb, p_attnapp);

    // 5. combine: cat(emb, attn_applied) @ comb_W^T, split-K 16
    gemm_f32x2<<<dim3(8, 16, 1), 128>>>(p_emb, p_attnapp, EE, EE + HH, combW,
                                        p_pa, EE, 128, nullptr, nullptr, nullptr);

    // 6. reduce + bias + relu
    k_combrelu<<<(BB * EE) / 256, 256>>>(p_pa, combb, p_x, 16);

    // 7. GRU gi and gh, split-K 8 each
    gemm_f32x2<<<dim3(24, 8, 2), 128>>>(p_x, nullptr, HH, HH, Wih,
                                        p_pa, 3 * HH, 128,
                                        hidden, Whh, p_pb);

    // 8. GRU gate fusion -> new hidden
    k_gru<<<(BB * HH) / 256, 256>>>(p_pa, p_pb, bih, bhh, hidden, newh, 8);

    // 9. output projection via bf16 tensor cores
    k_outproj<<<(VV + 127) / 128, 256>>>(newh, outW, outb, out);

    // 10. split log_softmax over vocab
    k_lsm_part<<<dim3(8, BB), 256>>>(out, p_lsm);
    k_lsm_comb<<<BB, 32>>>(p_lsm);
    k_lsm_write<<<dim3(8, BB), 256>>>(out, p_lsm);
}

// round 3
// speedup vs baseline: 3.2809x; 1.5766x over previous
#include <cuda_runtime.h>
#include <math.h>
#include <stdint.h>

#define BB 64
#define EE 1024
#define HH 1024
#define LL 512
#define VV 50257
#define NBLK_OUT 393   // ceil(VV/128)

// ---------------- scratch (device globals, no allocation) ----------------
__device__ float g_attnw[BB * LL];
__device__ float g_attnapp[BB * HH];
__device__ float g_x[BB * EE];
__device__ float g_partA[8 * BB * 3 * HH];   // 1.57M floats
__device__ float g_partB[8 * BB * 3 * HH];
__device__ float g_pmax[64 * 512];
__device__ float g_psum[64 * 512];
__device__ float g_lse[64];

// ---------------- helpers ----------------
__device__ __forceinline__ uint32_t pack_bf16(float lo, float hi) {
    uint32_t r;
    asm("cvt.rn.bf16x2.f32 %0, %1, %2;" : "=r"(r) : "f"(hi), "f"(lo));
    return r;
}
// 128B atoms: (8 rows x 8 k) bf16; 8 k-chunks; XOR slotting for conflict-free ldmatrix
__device__ __forceinline__ int tile_off8(int row, int k) {
    int c = k >> 3;
    return (((row >> 3) << 3) + c) * 128 + (((row & 7) ^ c) << 4) + (k & 7) * 2;
}

// ================= unified bf16 tensor GEMM (split-K partials) =================
// Cpart[s][64][N] = A[64, kChunk-slice] @ W[N,K]^T.  BM=64 BN=128 BK=64, 256 thr.
// A = concat(A1[64,K1], A2[64,K-K1]); if gids, A1 rows gathered: A1 + gids[m]*K1.
// blockIdx.z==1 swaps in (A1b, Wb, Cb) with gather off (GRU gh).
__global__ __launch_bounds__(256) void gemm_bf16(
    const float* __restrict__ A1, const float* __restrict__ A2,
    const int* __restrict__ gids, int K1, int K,
    const float* __restrict__ W, float* __restrict__ C, int N, int kChunk,
    const float* A1b, const float* Wb, float* Cb) {
    if (blockIdx.z == 1) { A1 = A1b; W = Wb; C = Cb; gids = nullptr; }

    __shared__ __align__(16) uint32_t smA[2048];   // 64x64 bf16 = 8KB
    __shared__ __align__(16) uint32_t smB[4096];   // 128x64 bf16 = 16KB

    const int tid = threadIdx.x;
    const int lane = tid & 31, wid = tid >> 5;
    const int wm = wid & 1, wn = wid >> 1;
    const int nBase = blockIdx.x * 128;
    const int kBase = blockIdx.y * kChunk;
    const int tiles = kChunk >> 6;

    uint32_t aBase = (uint32_t)__cvta_generic_to_shared(smA);
    uint32_t bBase = (uint32_t)__cvta_generic_to_shared(smB);

    // per-lane address components
    int aAtom[2], aLow[2];
#pragma unroll
    for (int ma = 0; ma < 2; ma++) {
        int row = wm * 32 + ma * 16 + ((lane >> 3) & 1) * 8 + (lane & 7);
        aAtom[ma] = (row >> 3) << 10;   // *8 atoms *128B
        aLow[ma] = row & 7;
    }
    const int aCbit = lane >> 4;
    int bAtom[4], bLow[4];
    const int ll = lane & 15;
#pragma unroll
    for (int na = 0; na < 4; na++) {
        int n = wn * 32 + na * 8 + (ll & 7);
        bAtom[na] = (n >> 3) << 10;
        bLow[na] = n & 7;
    }
    const int bCbit = ll >> 3;

    float acc[2][4][4];
#pragma unroll
    for (int i = 0; i < 2; i++)
#pragma unroll
        for (int j = 0; j < 4; j++)
#pragma unroll
            for (int q = 0; q < 4; q++) acc[i][j][q] = 0.f;

    float4 ra[4], rb[8];
    const int arow = tid >> 4, ac4 = tid & 15;

    auto loadA = [&](int k0) {
#pragma unroll
        for (int s = 0; s < 4; s++) {
            int row = arow + 16 * s;
            int k = k0 + ac4 * 4;
            const float* rp;
            if (k < K1) rp = (gids ? A1 + (size_t)gids[row] * K1 : A1 + (size_t)row * K1) + k;
            else        rp = A2 + (size_t)row * (K - K1) + (k - K1);
            ra[s] = *reinterpret_cast<const float4*>(rp);
        }
    };
    auto loadB = [&](int k0) {
#pragma unroll
        for (int s = 0; s < 8; s++) {
            int row = arow + 16 * s;
            rb[s] = *reinterpret_cast<const float4*>(W + (size_t)(nBase + row) * K + k0 + ac4 * 4);
        }
    };

    loadA(kBase);
    loadB(kBase);

    for (int kt = 0; kt < tiles; kt++) {
        __syncthreads();
#pragma unroll
        for (int s = 0; s < 4; s++) {
            uint2 v = make_uint2(pack_bf16(ra[s].x, ra[s].y), pack_bf16(ra[s].z, ra[s].w));
            *reinterpret_cast<uint2*>(reinterpret_cast<char*>(smA) + tile_off8(arow + 16 * s, ac4 * 4)) = v;
        }
#pragma unroll
        for (int s = 0; s < 8; s++) {
            uint2 v = make_uint2(pack_bf16(rb[s].x, rb[s].y), pack_bf16(rb[s].z, rb[s].w));
            *reinterpret_cast<uint2*>(reinterpret_cast<char*>(smB) + tile_off8(arow + 16 * s, ac4 * 4)) = v;
        }
        __syncthreads();
        if (kt + 1 < tiles) {
            loadA(kBase + (kt + 1) * 64);
            loadB(kBase + (kt + 1) * 64);
        }
#pragma unroll
        for (int ka = 0; ka < 4; ka++) {
            uint32_t af[2][4];
#pragma unroll
            for (int ma = 0; ma < 2; ma++) {
                int c = ka * 2 + aCbit;
                uint32_t ad = aBase + aAtom[ma] + c * 128 + ((aLow[ma] ^ c) << 4);
                asm volatile("ldmatrix.sync.aligned.m8n8.x4.shared.b16 {%0,%1,%2,%3}, [%4];"
                             : "=r"(af[ma][0]), "=r"(af[ma][1]), "=r"(af[ma][2]), "=r"(af[ma][3])
                             : "r"(ad));
            }
            uint32_t bf[4][2];
#pragma unroll
            for (int na = 0; na < 4; na++) {
                int c = ka * 2 + bCbit;
                uint32_t bd = bBase + bAtom[na] + c * 128 + ((bLow[na] ^ c) << 4);
                asm volatile("ldmatrix.sync.aligned.m8n8.x2.shared.b16 {%0,%1}, [%2];"
                             : "=r"(bf[na][0]), "=r"(bf[na][1]) : "r"(bd));
            }
#pragma unroll
            for (int ma = 0; ma < 2; ma++)
#pragma unroll
                for (int na = 0; na < 4; na++)
                    asm volatile(
                        "mma.sync.aligned.m16n8k16.row.col.f32.bf16.bf16.f32 "
                        "{%0,%1,%2,%3}, {%4,%5,%6,%7}, {%8,%9}, {%0,%1,%2,%3};"
                        : "+f"(acc[ma][na][0]), "+f"(acc[ma][na][1]),
                          "+f"(acc[ma][na][2]), "+f"(acc[ma][na][3])
                        : "r"(af[ma][0]), "r"(af[ma][1]), "r"(af[ma][2]), "r"(af[ma][3]),
                          "r"(bf[na][0]), "r"(bf[na][1]));
        }
    }

    float* Cout = C + (size_t)blockIdx.y * 64 * N;
    int g = lane >> 2, tig = lane & 3;
#pragma unroll
    for (int ma = 0; ma < 2; ma++)
#pragma unroll
        for (int na = 0; na < 4; na++) {
            int col = nBase + wn * 32 + na * 8 + tig * 2;
            int r0 = wm * 32 + ma * 16 + g;
            *reinterpret_cast<float2*>(Cout + (size_t)r0 * N + col) =
                make_float2(acc[ma][na][0], acc[ma][na][1]);
            *reinterpret_cast<float2*>(Cout + (size_t)(r0 + 8) * N + col) =
                make_float2(acc[ma][na][2], acc[ma][na][3]);
        }
}

// ================= fat output GEMM + bias + fused lsm partials =================
__global__ __launch_bounds__(256) void k_outproj(const float* __restrict__ A,
                                                 const float* __restrict__ W,
                                                 const float* __restrict__ bias,
                                                 float* __restrict__ C,
                                                 float* __restrict__ pmax,
                                                 float* __restrict__ psum) {
    __shared__ __align__(16) uint32_t smA[2048];   // 64x64 bf16
    __shared__ __align__(16) uint32_t smB[4096];   // 128x64 bf16
    __shared__ float redMax[64][4];
    __shared__ float redSum[64][4];

    const int tid = threadIdx.x;
    const int lane = tid & 31, wid = tid >> 5;
    const int wm = wid & 1, wn = wid >> 1;
    const int nBase = blockIdx.x * 128;

    uint32_t aBase = (uint32_t)__cvta_generic_to_shared(smA);
    uint32_t bBase = (uint32_t)__cvta_generic_to_shared(smB);

    int aAtom[2], aLow[2];
#pragma unroll
    for (int ma = 0; ma < 2; ma++) {
        int row = wm * 32 + ma * 16 + ((lane >> 3) & 1) * 8 + (lane & 7);
        aAtom[ma] = (row >> 3) << 10;
        aLow[ma] = row & 7;
    }
    const int aCbit = lane >> 4;
    int bAtom[4], bLow[4];
    const int ll = lane & 15;
#pragma unroll
    for (int na = 0; na < 4; na++) {
        int n = wn * 32 + na * 8 + (ll & 7);
        bAtom[na] = (n >> 3) << 10;
        bLow[na] = n & 7;
    }
    const int bCbit = ll >> 3;

    float acc[2][4][4];
#pragma unroll
    for (int i = 0; i < 2; i++)
#pragma unroll
        for (int j = 0; j < 4; j++)
#pragma unroll
            for (int q = 0; q < 4; q++) acc[i][j][q] = 0.f;

    float4 ra[4], rb[8];
    const int arow = tid >> 4, ac4 = tid & 15;

    auto loadA = [&](int k0) {
#pragma unroll
        for (int s = 0; s < 4; s++)
            ra[s] = *reinterpret_cast<const float4*>(A + (size_t)(arow + 16 * s) * 1024 + k0 + ac4 * 4);
    };
    auto loadB = [&](int k0) {
#pragma unroll
        for (int s = 0; s < 8; s++) {
            int ng = nBase + arow + 16 * s;
            if (ng < VV)
                rb[s] = *reinterpret_cast<const float4*>(W + (size_t)ng * 1024 + k0 + ac4 * 4);
            else
                rb[s] = make_float4(0.f, 0.f, 0.f, 0.f);
        }
    };

    loadA(0);
    loadB(0);

    for (int kt = 0; kt < 16; kt++) {
        __syncthreads();
#pragma unroll
        for (int s = 0; s < 4; s++) {
            uint2 v = make_uint2(pack_bf16(ra[s].x, ra[s].y), pack_bf16(ra[s].z, ra[s].w));
            *reinterpret_cast<uint2*>(reinterpret_cast<char*>(smA) + tile_off8(arow + 16 * s, ac4 * 4)) = v;
        }
#pragma unroll
        for (int s = 0; s < 8; s++) {
            uint2 v = make_uint2(pack_bf16(rb[s].x, rb[s].y), pack_bf16(rb[s].z, rb[s].w));
            *reinterpret_cast<uint2*>(reinterpret_cast<char*>(smB) + tile_off8(arow + 16 * s, ac4 * 4)) = v;
        }
        __syncthreads();
        if (kt + 1 < 16) {
            loadA((kt + 1) * 64);
            loadB((kt + 1) * 64);
        }
#pragma unroll
        for (int ka = 0; ka < 4; ka++) {
            uint32_t af[2][4];
#pragma unroll
            for (int ma = 0; ma < 2; ma++) {
                int c = ka * 2 + aCbit;
                uint32_t ad = aBase + aAtom[ma] + c * 128 + ((aLow[ma] ^ c) << 4);
                asm volatile("ldmatrix.sync.aligned.m8n8.x4.shared.b16 {%0,%1,%2,%3}, [%4];"
                             : "=r"(af[ma][0]), "=r"(af[ma][1]), "=r"(af[ma][2]), "=r"(af[ma][3])
                             : "r"(ad));
            }
            uint32_t bf[4][2];
#pragma unroll
            for (int na = 0; na < 4; na++) {
                int c = ka * 2 + bCbit;
                uint32_t bd = bBase + bAtom[na] + c * 128 + ((bLow[na] ^ c) << 4);
                asm volatile("ldmatrix.sync.aligned.m8n8.x2.shared.b16 {%0,%1}, [%2];"
                             : "=r"(bf[na][0]), "=r"(bf[na][1]) : "r"(bd));
            }
#pragma unroll
            for (int ma = 0; ma < 2; ma++)
#pragma unroll
                for (int na = 0; na < 4; na++)
                    asm volatile(
                        "mma.sync.aligned.m16n8k16.row.col.f32.bf16.bf16.f32 "
                        "{%0,%1,%2,%3}, {%4,%5,%6,%7}, {%8,%9}, {%0,%1,%2,%3};"
                        : "+f"(acc[ma][na][0]), "+f"(acc[ma][na][1]),
                          "+f"(acc[ma][na][2]), "+f"(acc[ma][na][3])
                        : "r"(af[ma][0]), "r"(af[ma][1]), "r"(af[ma][2]), "r"(af[ma][3]),
                          "r"(bf[na][0]), "r"(bf[na][1]));
        }
    }

    // epilogue: bias add, store C, per-row max/sumexp partials
    int g = lane >> 2, tig = lane & 3;
#pragma unroll
    for (int ma = 0; ma < 2; ma++)
#pragma unroll
        for (int na = 0; na < 4; na++) {
            int col = nBase + wn * 32 + na * 8 + tig * 2;
            int r0 = wm * 32 + ma * 16 + g;
            if (col < VV) {
                float b0 = bias[col];
                acc[ma][na][0] += b0; acc[ma][na][2] += b0;
                C[(size_t)r0 * VV + col]       = acc[ma][na][0];
                C[(size_t)(r0 + 8) * VV + col] = acc[ma][na][2];
            } else { acc[ma][na][0] = -1e30f; acc[ma][na][2] = -1e30f; }
            if (col + 1 < VV) {
                float b1 = bias[col + 1];
                acc[ma][na][1] += b1; acc[ma][na][3] += b1;
                C[(size_t)r0 * VV + col + 1]       = acc[ma][na][1];
                C[(size_t)(r0 + 8) * VV + col + 1] = acc[ma][na][3];
            } else { acc[ma][na][1] = -1e30f; acc[ma][na][3] = -1e30f; }
        }

    float lm[2][2];
#pragma unroll
    for (int ma = 0; ma < 2; ma++) {
        float m0 = -1e30f, m1 = -1e30f;
#pragma unroll
        for (int na = 0; na < 4; na++) {
            m0 = fmaxf(m0, fmaxf(acc[ma][na][0], acc[ma][na][1]));
            m1 = fmaxf(m1, fmaxf(acc[ma][na][2], acc[ma][na][3]));
        }
        m0 = fmaxf(m0, __shfl_xor_sync(~0u, m0, 1));
        m0 = fmaxf(m0, __shfl_xor_sync(~0u, m0, 2));
        m1 = fmaxf(m1, __shfl_xor_sync(~0u, m1, 1));
        m1 = fmaxf(m1, __shfl_xor_sync(~0u, m1, 2));
        lm[ma][0] = m0; lm[ma][1] = m1;
        if (tig == 0) {
            redMax[wm * 32 + ma * 16 + g][wn] = m0;
            redMax[wm * 32 + ma * 16 + g + 8][wn] = m1;
        }
    }
    __syncthreads();
#pragma unroll
    for (int ma = 0; ma < 2; ma++)
#pragma unroll
        for (int h = 0; h < 2; h++) {
            int row = wm * 32 + ma * 16 + g + h * 8;
            float rm = fmaxf(fmaxf(redMax[row][0], redMax[row][1]),
                             fmaxf(redMax[row][2], redMax[row][3]));
            float s = 0.f;
#pragma unroll
            for (int na = 0; na < 4; na++) {
                s += __expf(acc[ma][na][h * 2] - rm);
                s += __expf(acc[ma][na][h * 2 + 1] - rm);
            }
            s += __shfl_xor_sync(~0u, s, 1);
            s += __shfl_xor_sync(~0u, s, 2);
            if (tig == 0) redSum[row][wn] = s;
        }
    __syncthreads();
    if (tid < 64) {
        float rm = fmaxf(fmaxf(redMax[tid][0], redMax[tid][1]),
                         fmaxf(redMax[tid][2], redMax[tid][3]));
        float s = redSum[tid][0] + redSum[tid][1] + redSum[tid][2] + redSum[tid][3];
        pmax[tid * 512 + blockIdx.x] = rm;
        psum[tid * 512 + blockIdx.x] = s;
    }
}

// ---------------- attn logits reduce + softmax over L=512 ----------------
__global__ void k_attn_softmax(const float* __restrict__ part, const float* __restrict__ bias,
                               float* __restrict__ wout) {
    int b = blockIdx.x;
    int l = threadIdx.x;
    float v = bias[l];
#pragma unroll
    for (int s = 0; s < 16; s++) v += part[((size_t)s * BB + b) * LL + l];

    __shared__ float red[32];
    float m = v;
#pragma unroll
    for (int o = 16; o > 0; o >>= 1) m = fmaxf(m, __shfl_xor_sync(~0u, m, o));
    if ((threadIdx.x & 31) == 0) red[threadIdx.x >> 5] = m;
    __syncthreads();
    if (threadIdx.x < 32) {
        float t = (threadIdx.x < 16) ? red[threadIdx.x] : -1e30f;
#pragma unroll
        for (int o = 8; o > 0; o >>= 1) t = fmaxf(t, __shfl_xor_sync(~0u, t, o));
        if (threadIdx.x == 0) red[0] = t;
    }
    __syncthreads();
    float rowmax = red[0];
    __syncthreads();
    float e = expf(v - rowmax);
    float ssum = e;
#pragma unroll
    for (int o = 16; o > 0; o >>= 1) ssum += __shfl_xor_sync(~0u, ssum, o);
    if ((threadIdx.x & 31) == 0) red[threadIdx.x >> 5] = ssum;
    __syncthreads();
    if (threadIdx.x < 32) {
        float t = (threadIdx.x < 16) ? red[threadIdx.x] : 0.f;
#pragma unroll
        for (int o = 8; o > 0; o >>= 1) t += __shfl_xor_sync(~0u, t, o);
        if (threadIdx.x == 0) red[0] = t;
    }
    __syncthreads();
    wout[b * LL + l] = e / red[0];
}

// ---------------- attn context partials: 16 slices of 32 L-rows ----------------
__global__ void k_attnapp_part(const float* __restrict__ w, const float* __restrict__ enc,
                               float* __restrict__ part) {
    int s = blockIdx.x;
    int b = blockIdx.y;
    int d4 = threadIdx.x;
    __shared__ float ws[32];
    if (threadIdx.x < 32) ws[threadIdx.x] = w[b * LL + s * 32 + threadIdx.x];
    __syncthreads();
    const float4* ep = reinterpret_cast<const float4*>(enc + (size_t)b * LL * HH + (size_t)s * 32 * HH) + d4;
    float4 acc = make_float4(0.f, 0.f, 0.f, 0.f);
#pragma unroll 8
    for (int l = 0; l < 32; l++) {
        float4 v = ep[l * (HH / 4)];
        float c = ws[l];
        acc.x += c * v.x; acc.y += c * v.y; acc.z += c * v.z; acc.w += c * v.w;
    }
    reinterpret_cast<float4*>(part + ((size_t)s * BB + b) * HH)[d4] = acc;
}

__global__ void k_attnred(const float* __restrict__ part, float* __restrict__ out) {
    int i = blockIdx.x * 256 + threadIdx.x;
    float v = 0.f;
#pragma unroll
    for (int s = 0; s < 16; s++) v += part[(size_t)s * BB * HH + i];
    out[i] = v;
}

// ---------------- combine reduce + bias + relu ----------------
__global__ void k_combrelu(const float* __restrict__ part, const float* __restrict__ bias,
                           float* __restrict__ out) {
    int idx = blockIdx.x * 256 + threadIdx.x;
    int e = idx & (EE - 1);
    float v = bias[e];
#pragma unroll
    for (int s = 0; s < 16; s++) v += part[(size_t)s * BB * EE + idx];
    out[idx] = fmaxf(v, 0.f);
}

// ---------------- GRU gates ----------------
__global__ void k_gru(const float* __restrict__ pgi, const float* __restrict__ pgh,
                      const float* __restrict__ bih, const float* __restrict__ bhh,
                      const float* __restrict__ hidden, float* __restrict__ newh) {
    int idx = blockIdx.x * 256 + threadIdx.x;
    int b = idx >> 10;
    int h = idx & 1023;
    const int N3 = 3 * HH;
    float ir = bih[h], iz = bih[HH + h], in_ = bih[2 * HH + h];
    float hr = bhh[h], hz = bhh[HH + h], hn = bhh[2 * HH + h];
#pragma unroll
    for (int s = 0; s < 8; s++) {
        size_t base = ((size_t)s * BB + b) * N3;
        ir  += pgi[base + h];
        iz  += pgi[base + HH + h];
        in_ += pgi[base + 2 * HH + h];
        hr  += pgh[base + h];
        hz  += pgh[base + HH + h];
        hn  += pgh[base + 2 * HH + h];
    }
    float r = 1.f / (1.f + expf(-(ir + hr)));
    float z = 1.f / (1.f + expf(-(iz + hz)));
    float n = tanhf(in_ + r * hn);
    newh[idx] = (1.f - z) * n + z * hidden[idx];
}

// ---------------- lsm combine + write ----------------
__global__ void k_lsm_comb(const float* __restrict__ pmax, const float* __restrict__ psum,
                           float* __restrict__ lse) {
    int row = blockIdx.x;
    __shared__ float red[32];
    float m = -1e30f;
    for (int c = threadIdx.x; c < NBLK_OUT; c += 128) m = fmaxf(m, pmax[row * 512 + c]);
#pragma unroll
    for (int o = 16; o > 0; o >>= 1) m = fmaxf(m, __shfl_xor_sync(~0u, m, o));
    if ((threadIdx.x & 31) == 0) red[threadIdx.x >> 5] = m;
    __syncthreads();
    if (threadIdx.x < 32) {
        float t = (threadIdx.x < 4) ? red[threadIdx.x] : -1e30f;
#pragma unroll
        for (int o = 2; o > 0; o >>= 1) t = fmaxf(t, __shfl_xor_sync(~0u, t, o));
        if (threadIdx.x == 0) red[0] = t;
    }
    __syncthreads();
    float M = red[0];
    __syncthreads();
    float s = 0.f;
    for (int c = threadIdx.x; c < NBLK_OUT; c += 128)
        s += psum[row * 512 + c] * __expf(pmax[row * 512 + c] - M);
#pragma unroll
    for (int o = 16; o > 0; o >>= 1) s += __shfl_xor_sync(~0u, s, o);
    if ((threadIdx.x & 31) == 0) red[threadIdx.x >> 5] = s;
    __syncthreads();
    if (threadIdx.x < 32) {
        float t = (threadIdx.x < 4) ? red[threadIdx.x] : 0.f;
#pragma unroll
        for (int o = 2; o > 0; o >>= 1) t += __shfl_xor_sync(~0u, t, o);
        if (threadIdx.x == 0) lse[row] = M + logf(t);
    }
}

__global__ void k_lsm_write(float* __restrict__ out, const float* __restrict__ lse) {
    int c = blockIdx.x;
    int b = blockIdx.y;
    const int CH = (VV + 7) / 8;
    int start = c * CH;
    int end = min(start + CH, VV);
    float L = lse[b];
    float* row = out + (size_t)b * VV;
    for (int i = start + threadIdx.x; i < end; i += 256) row[i] -= L;
}

// ---------------- launch ----------------
extern "C" void kernel_launch(void* const* d_in, const int* in_sizes, int n_in,
                              void* d_out, int out_size) {
    const int*   ids    = (const int*)  d_in[0];
    const float* hidden = (const float*)d_in[1];
    const float* enc    = (const float*)d_in[2];
    const float* embW   = (const float*)d_in[3];
    const float* attnW  = (const float*)d_in[4];
    const float* attnb  = (const float*)d_in[5];
    const float* combW  = (const float*)d_in[6];
    const float* combb  = (const float*)d_in[7];
    const float* Wih    = (const float*)d_in[8];
    const float* Whh    = (const float*)d_in[9];
    const float* bih    = (const float*)d_in[10];
    const float* bhh    = (const float*)d_in[11];
    const float* outW   = (const float*)d_in[12];
    const float* outb   = (const float*)d_in[13];

    float* out  = (float*)d_out;
    float* newh = out + (size_t)BB * VV;

    float *p_attnw, *p_attnapp, *p_x, *p_pa, *p_pb, *p_pmax, *p_psum, *p_lse;
    cudaGetSymbolAddress((void**)&p_attnw, g_attnw);
    cudaGetSymbolAddress((void**)&p_attnapp, g_attnapp);
    cudaGetSymbolAddress((void**)&p_x, g_x);
    cudaGetSymbolAddress((void**)&p_pa, g_partA);
    cudaGetSymbolAddress((void**)&p_pb, g_partB);
    cudaGetSymbolAddress((void**)&p_pmax, g_pmax);
    cudaGetSymbolAddress((void**)&p_psum, g_psum);
    cudaGetSymbolAddress((void**)&p_lse, g_lse);

    // 1. attn logits: cat(gather(emb), hidden) @ attn_W^T, split-K 16
    gemm_bf16<<<dim3(4, 16, 1), 256>>>(embW, hidden, ids, EE, EE + HH, attnW,
                                       p_pa, LL, 128, nullptr, nullptr, nullptr);

    // 2. reduce + bias + softmax over L
    k_attn_softmax<<<BB, 512>>>(p_pa, attnb, p_attnw);

    // 3. attention context (16 L-slices + reduce)
    k_attnapp_part<<<dim3(16, BB), 256>>>(p_attnw, enc, p_pb);
    k_attnred<<<(BB * HH) / 256, 256>>>(p_pb, p_attnapp);

    // 4. combine: cat(gather(emb), attn_applied) @ comb_W^T, split-K 16
    gemm_bf16<<<dim3(8, 16, 1), 256>>>(embW, p_attnapp, ids, EE, EE + HH, combW,
                                       p_pa, EE, 128, nullptr, nullptr, nullptr);
    k_combrelu<<<(BB * EE) / 256, 256>>>(p_pa, combb, p_x);

    // 5. GRU gi (z=0) and gh (z=1), split-K 8
    gemm_bf16<<<dim3(24, 8, 2), 256>>>(p_x, nullptr, nullptr, HH, HH, Wih,
                                       p_pa, 3 * HH, 128,
                                       hidden, Whh, p_pb);
    k_gru<<<(BB * HH) / 256, 256>>>(p_pa, p_pb, bih, bhh, hidden, newh);

    // 6. output projection (bf16 tensor) + fused lsm partials
    k_outproj<<<NBLK_OUT, 256>>>(newh, outW, outb, out, p_pmax, p_psum);

    // 7. lsm combine + write
    k_lsm_comb<<<BB, 128>>>(p_pmax, p_psum, p_lse);
    k_lsm_write<<<dim3(8, BB), 256>>>(out, p_lse);
}